// round 11
// baseline (speedup 1.0000x reference)
#include <cuda_runtime.h>
#include <cstdint>

namespace {
constexpr int Bb = 16384, Ss = 5, Dd = 512, Hh = 8, HDd = 64;
constexpr int Mm = Bb * Ss;               // 81920
constexpr int BM = 128, BN = 128, BK = 32;
constexpr int KITERS = Dd / BK;           // 16
constexpr int TSTRIDE = 36;               // [128][36] tiles, ldmatrix conflict-free
constexpr int TILE_F = BM * TSTRIDE;      // 4608 floats per tile
constexpr int STAGE_F = 2 * TILE_F;       // A + B = 9216 floats = 36864 B
constexpr int STAGES = 3;
constexpr int SMEM_BYTES = STAGES * STAGE_F * 4;  // 110592 B
}

// Scratch (device globals: allocation-free rule)
__device__ float g_QKV[(size_t)Mm * 1536];  // [m][ q | k | v ]
__device__ float g_O[(size_t)Mm * Dd];      // rna(attn out)
__device__ float g_Wt[4 * 512 * 512];       // rna(W^T): [w][n][k]

__device__ __forceinline__ float to_tf32(float x) {
  float y;
  asm("cvt.rna.tf32.f32 %0, %1;" : "=f"(y) : "f"(x));
  return y;
}
__device__ __forceinline__ uint32_t cvt_u(uint32_t x) {
  return __float_as_uint(to_tf32(__uint_as_float(x)));
}

__device__ __forceinline__ void mma_tf32(float c[4], uint32_t a0, uint32_t a1,
                                         uint32_t a2, uint32_t a3,
                                         uint32_t b0, uint32_t b1) {
  asm volatile(
      "mma.sync.aligned.m16n8k8.row.col.f32.tf32.tf32.f32 "
      "{%0,%1,%2,%3}, {%4,%5,%6,%7}, {%8,%9}, {%0,%1,%2,%3};"
      : "+f"(c[0]), "+f"(c[1]), "+f"(c[2]), "+f"(c[3])
      : "r"(a0), "r"(a1), "r"(a2), "r"(a3), "r"(b0), "r"(b1));
}

__device__ __forceinline__ void ldmatrix_x4(uint32_t r[4], uint32_t addr) {
  asm volatile(
      "ldmatrix.sync.aligned.m8n8.x4.shared.b16 {%0,%1,%2,%3}, [%4];"
      : "=r"(r[0]), "=r"(r[1]), "=r"(r[2]), "=r"(r[3])
      : "r"(addr));
}

__device__ __forceinline__ void cp_async16(void* smem_ptr, const void* gptr) {
  uint32_t saddr = (uint32_t)__cvta_generic_to_shared(smem_ptr);
  asm volatile("cp.async.cg.shared.global [%0], [%1], 16;" ::"r"(saddr),
               "l"(gptr));
}
__device__ __forceinline__ void cp_commit() {
  asm volatile("cp.async.commit_group;" ::);
}

// Out[:, col0:col0+128] = A[M,512] @ Wt_sec^T + bias_sec
// Wt is PRE-ROUNDED tf32 in [n][k] layout. A: CVT_A -> rna per frag, else RZ.
template <bool CVT_A>
__global__ __launch_bounds__(256, 2) void gemm_tf32_kernel(
    const float* __restrict__ A, const float* __restrict__ Wt0,
    const float* __restrict__ Wt1, const float* __restrict__ Wt2,
    const float* __restrict__ bias0, const float* __restrict__ bias1,
    const float* __restrict__ bias2, float* __restrict__ Out, int ostride) {
  extern __shared__ float smem[];
  const uint32_t sb = (uint32_t)__cvta_generic_to_shared(smem);

  const int tid = threadIdx.x;
  const int m0 = blockIdx.y * BM;
  const int col0 = blockIdx.x * BN;
  const int sec = col0 >> 9;
  const int n0 = col0 & 511;
  const float* Wt = (sec == 0) ? Wt0 : ((sec == 1) ? Wt1 : Wt2);
  const float* bias = (sec == 0) ? bias0 : ((sec == 1) ? bias1 : bias2);

  const int warp = tid >> 5, lane = tid & 31;
  const int g = lane >> 2, t = lane & 3;
  const int warp_m = (warp >> 2) * 64;  // 2 warps in m
  const int warp_n = (warp & 3) * 32;   // 4 warps in n

  // ldmatrix lane->row/byte map (x4: lanes 0-7 m0, 8-15 m1, 16-23 m2, 24-31 m3)
  const int lm_row = (lane & 7) + ((lane >> 3) & 1) * 8;
  const uint32_t lm_byte = ((lane >> 4) & 1) * 16;
  const uint32_t a_lane_off =
      (uint32_t)((warp_m + lm_row) * (TSTRIDE * 4)) + lm_byte;
  const uint32_t b_lane_off =
      (uint32_t)((warp_n + lm_row) * (TSTRIDE * 4)) + lm_byte;

  float acc[4][4][4];
#pragma unroll
  for (int i = 0; i < 4; i++)
#pragma unroll
    for (int j = 0; j < 4; j++)
#pragma unroll
      for (int r = 0; r < 4; r++) acc[i][j][r] = 0.f;

  auto issue_stage = [&](int it) {
    float* as = smem + (it % STAGES) * STAGE_F;
    float* bs = as + TILE_F;
    const int k0 = it * BK;
    // A tile: 128 rows x 32 floats (1024 chunks, 4/thread)
#pragma unroll
    for (int i = 0; i < 4; i++) {
      int cid = tid + i * 256;
      int row = cid >> 3, q = (cid & 7) * 4;
      cp_async16(as + row * TSTRIDE + q,
                 A + (size_t)(m0 + row) * Dd + k0 + q);
    }
    // B tile: 128 n-rows x 32 k-floats from Wt [n][k]
#pragma unroll
    for (int i = 0; i < 4; i++) {
      int cid = tid + i * 256;
      int row = cid >> 3, q = (cid & 7) * 4;
      cp_async16(bs + row * TSTRIDE + q,
                 Wt + (size_t)(n0 + row) * Dd + k0 + q);
    }
    cp_commit();
  };

  issue_stage(0);
  issue_stage(1);

  for (int it = 0; it < KITERS; it++) {
    if (it < KITERS - 1)
      asm volatile("cp.async.wait_group 1;" ::: "memory");
    else
      asm volatile("cp.async.wait_group 0;" ::: "memory");
    __syncthreads();  // single barrier per iter
    if (it + 2 < KITERS) issue_stage(it + 2);

    const uint32_t stage_base = sb + (uint32_t)((it % STAGES) * STAGE_F * 4);
    const uint32_t a_base = stage_base + a_lane_off;
    const uint32_t b_base = stage_base + (uint32_t)(TILE_F * 4) + b_lane_off;
#pragma unroll
    for (int ks = 0; ks < BK; ks += 8) {
      uint32_t af[4][4], bf[4][2];
#pragma unroll
      for (int mi = 0; mi < 4; mi++) {
        ldmatrix_x4(af[mi], a_base + mi * (16 * TSTRIDE * 4) + ks * 4);
        if (CVT_A) {
#pragma unroll
          for (int r = 0; r < 4; r++) af[mi][r] = cvt_u(af[mi][r]);
        }
      }
      // B frags: one x4 covers two ni blocks (16 n-cols) with b0+b1
#pragma unroll
      for (int nb = 0; nb < 2; nb++) {
        uint32_t br[4];
        ldmatrix_x4(br, b_base + nb * (16 * TSTRIDE * 4) + ks * 4);
        bf[nb * 2 + 0][0] = br[0];  // n block +0..7:  b0 (k=t)
        bf[nb * 2 + 0][1] = br[2];  //                 b1 (k=t+4)
        bf[nb * 2 + 1][0] = br[1];  // n block +8..15: b0
        bf[nb * 2 + 1][1] = br[3];  //                 b1
      }
#pragma unroll
      for (int mi = 0; mi < 4; mi++)
#pragma unroll
        for (int ni = 0; ni < 4; ni++)
          mma_tf32(acc[mi][ni], af[mi][0], af[mi][1], af[mi][2], af[mi][3],
                   bf[ni][0], bf[ni][1]);
    }
  }

  // epilogue: bias + store
#pragma unroll
  for (int mi = 0; mi < 4; mi++) {
    int r0 = m0 + warp_m + mi * 16 + g;
#pragma unroll
    for (int ni = 0; ni < 4; ni++) {
      int c = col0 + warp_n + ni * 8 + 2 * t;
      float b0v = bias[c & 511], b1v = bias[(c & 511) + 1];
      float2 v0 = make_float2(acc[mi][ni][0] + b0v, acc[mi][ni][1] + b1v);
      float2 v1 = make_float2(acc[mi][ni][2] + b0v, acc[mi][ni][3] + b1v);
      *reinterpret_cast<float2*>(Out + (size_t)r0 * ostride + c) = v0;
      *reinterpret_cast<float2*>(Out + (size_t)(r0 + 8) * ostride + c) = v1;
    }
  }
}

// Weight transpose + rna: Wt[w][n][k] = rna(W_w[k][n]). 32x32 smem tiles.
__global__ void transpose_w_kernel(const float* __restrict__ Wq,
                                   const float* __restrict__ Wk,
                                   const float* __restrict__ Wv,
                                   const float* __restrict__ Wo) {
  __shared__ float s[32][33];
  const int w = blockIdx.z;
  const float* W = (w == 0) ? Wq : (w == 1) ? Wk : (w == 2) ? Wv : Wo;
  float* Wt = g_Wt + (size_t)w * 262144;
  const int k0 = blockIdx.x * 32, n0 = blockIdx.y * 32;
  const int tx = threadIdx.x, ty = threadIdx.y;
#pragma unroll
  for (int i = ty; i < 32; i += 8)
    s[i][tx] = to_tf32(W[(size_t)(k0 + i) * 512 + n0 + tx]);
  __syncthreads();
#pragma unroll
  for (int i = ty; i < 32; i += 8)
    Wt[(size_t)(n0 + i) * 512 + k0 + tx] = s[tx][i];
}

// 512 threads, 2 batches per CTA; warp (h within half) = head h.
__global__ __launch_bounds__(512) void attn_kernel(const float* __restrict__ pb) {
  __shared__ float sX[2][Ss * 1536];
  __shared__ float sA[2][Hh][Ss][Ss];
  const int b2 = blockIdx.x;
  const int tid = threadIdx.x;
  const float* src = g_QKV + (size_t)b2 * (2 * Ss * 1536);

  for (int i = tid; i < 2 * Ss * 1536 / 4; i += 512)
    reinterpret_cast<float4*>(&sX[0][0])[i] =
        reinterpret_cast<const float4*>(src)[i];
  __syncthreads();

  const int half = tid >> 8;
  const int h = (tid >> 5) & 7, lane = tid & 31;
  const int c0 = h * HDd;
  const float* X = sX[half];
  float (*Arow)[Ss] = sA[half][h];

  if (lane < Ss * Ss) {
    int s = lane / Ss, tt = lane % Ss;
    float a = 0.f;
#pragma unroll
    for (int d = 0; d < HDd; d++)
      a += X[s * 1536 + c0 + d] * X[tt * 1536 + 512 + c0 + d];
    Arow[s][tt] = a * 0.125f + pb[(h * Ss + s) * Ss + tt];
  }
  __syncwarp();

  if (lane < Ss) {
    float m = Arow[lane][0];
#pragma unroll
    for (int tt = 1; tt < Ss; tt++) m = fmaxf(m, Arow[lane][tt]);
    float e[Ss], sum = 0.f;
#pragma unroll
    for (int tt = 0; tt < Ss; tt++) {
      e[tt] = expf(Arow[lane][tt] - m);
      sum += e[tt];
    }
    float inv = 1.0f / sum;
#pragma unroll
    for (int tt = 0; tt < Ss; tt++) Arow[lane][tt] = e[tt] * inv;
  }
  __syncwarp();

  float* dst = g_O + ((size_t)b2 * 2 + half) * (Ss * Dd);
#pragma unroll
  for (int s = 0; s < Ss; s++) {
    float o0 = 0.f, o1 = 0.f;
#pragma unroll
    for (int tt = 0; tt < Ss; tt++) {
      float a = Arow[s][tt];
      o0 += a * X[tt * 1536 + 1024 + c0 + lane];
      o1 += a * X[tt * 1536 + 1024 + c0 + lane + 32];
    }
    dst[s * Dd + c0 + lane] = to_tf32(o0);
    dst[s * Dd + c0 + lane + 32] = to_tf32(o1);
  }
}

extern "C" void kernel_launch(void* const* d_in, const int* in_sizes, int n_in,
                              void* d_out, int out_size) {
  (void)in_sizes; (void)n_in; (void)out_size;
  const float* x  = (const float*)d_in[0];
  const float* Wq = (const float*)d_in[1];
  const float* bq = (const float*)d_in[2];
  const float* Wk = (const float*)d_in[3];
  const float* bk = (const float*)d_in[4];
  const float* Wv = (const float*)d_in[5];
  const float* bv = (const float*)d_in[6];
  const float* Wo = (const float*)d_in[7];
  const float* bo = (const float*)d_in[8];
  const float* pb = (const float*)d_in[9];
  float* out = (float*)d_out;

  cudaFuncSetAttribute(gemm_tf32_kernel<true>,
                       cudaFuncAttributeMaxDynamicSharedMemorySize, SMEM_BYTES);
  cudaFuncSetAttribute(gemm_tf32_kernel<false>,
                       cudaFuncAttributeMaxDynamicSharedMemorySize, SMEM_BYTES);

  void *qkv = nullptr, *op = nullptr, *wt = nullptr;
  cudaGetSymbolAddress(&qkv, g_QKV);
  cudaGetSymbolAddress(&op, g_O);
  cudaGetSymbolAddress(&wt, g_Wt);
  float* Wt = (float*)wt;

  // 0) transpose + pre-round weights
  transpose_w_kernel<<<dim3(16, 16, 4), dim3(32, 8)>>>(Wq, Wk, Wv, Wo);

  // 1) fused QKV projection (A rna'd per fragment)
  gemm_tf32_kernel<true><<<dim3(1536 / BN, Mm / BM), 256, SMEM_BYTES>>>(
      x, Wt + 0 * 262144, Wt + 1 * 262144, Wt + 2 * 262144,
      bq, bk, bv, (float*)qkv, 1536);
  // 2) attention, 2 batches per CTA
  attn_kernel<<<Bb / 2, 512>>>(pb);
  // 3) output projection (A already rna'd by attn)
  gemm_tf32_kernel<false><<<dim3(512 / BN, Mm / BM), 256, SMEM_BYTES>>>(
      (const float*)op, Wt + 3 * 262144, Wt + 3 * 262144, Wt + 3 * 262144,
      bo, bo, bo, out, 512);
}

// round 12
// speedup vs baseline: 1.0803x; 1.0803x over previous
#include <cuda_runtime.h>
#include <cstdint>

namespace {
constexpr int Bb = 16384, Ss = 5, Dd = 512, Hh = 8, HDd = 64;
constexpr int Mm = Bb * Ss;               // 81920
constexpr int BM = 128, BN = 128, BK = 32;
constexpr int KITERS = Dd / BK;           // 16
constexpr int SA_STRIDE = 36;             // 144B rows: ldmatrix phases conflict-free
constexpr int SB_STRIDE = 136;            // conflict-free b-frag LDS (8t+g)
constexpr int A_STAGE = BM * SA_STRIDE;   // 4608 floats
constexpr int B_STAGE = BK * SB_STRIDE;   // 4352 floats
constexpr int STAGE_F = A_STAGE + B_STAGE;        // 8960 floats = 35840 B
constexpr int STAGES = 3;
constexpr int SMEM_BYTES = STAGES * STAGE_F * 4;  // 107520 B
}

// Scratch (device globals: allocation-free rule)
__device__ float g_QKV[(size_t)Mm * 1536];  // [m][ q | k | v ]
__device__ float g_O[(size_t)Mm * Dd];      // rna(attn out)
__device__ float g_Wr[4 * 512 * 512];       // rna(Wq|Wk|Wv|Wo), [k][n] layout

__device__ __forceinline__ float to_tf32(float x) {
  float y;
  asm("cvt.rna.tf32.f32 %0, %1;" : "=f"(y) : "f"(x));
  return y;
}
__device__ __forceinline__ uint32_t cvt_u(uint32_t x) {
  return __float_as_uint(to_tf32(__uint_as_float(x)));
}

__device__ __forceinline__ void mma_tf32(float c[4], uint32_t a0, uint32_t a1,
                                         uint32_t a2, uint32_t a3,
                                         uint32_t b0, uint32_t b1) {
  asm volatile(
      "mma.sync.aligned.m16n8k8.row.col.f32.tf32.tf32.f32 "
      "{%0,%1,%2,%3}, {%4,%5,%6,%7}, {%8,%9}, {%0,%1,%2,%3};"
      : "+f"(c[0]), "+f"(c[1]), "+f"(c[2]), "+f"(c[3])
      : "r"(a0), "r"(a1), "r"(a2), "r"(a3), "r"(b0), "r"(b1));
}

__device__ __forceinline__ void ldmatrix_x4(uint32_t r[4], uint32_t addr) {
  asm volatile(
      "ldmatrix.sync.aligned.m8n8.x4.shared.b16 {%0,%1,%2,%3}, [%4];"
      : "=r"(r[0]), "=r"(r[1]), "=r"(r[2]), "=r"(r[3])
      : "r"(addr));
}

__device__ __forceinline__ void cp_async16(void* smem_ptr, const void* gptr) {
  uint32_t saddr = (uint32_t)__cvta_generic_to_shared(smem_ptr);
  asm volatile("cp.async.cg.shared.global [%0], [%1], 16;" ::"r"(saddr),
               "l"(gptr));
}
__device__ __forceinline__ void cp_commit() {
  asm volatile("cp.async.commit_group;" ::);
}

// Out[:, col0:col0+128] = A[M,512] @ W_sec[512,512] + bias_sec
// W is PRE-ROUNDED tf32 in [k][n] layout. A: CVT_A -> rna per frag (overlapped).
template <bool CVT_A>
__global__ __launch_bounds__(256, 2) void gemm_tf32_kernel(
    const float* __restrict__ A, const float* __restrict__ W0,
    const float* __restrict__ W1, const float* __restrict__ W2,
    const float* __restrict__ bias0, const float* __restrict__ bias1,
    const float* __restrict__ bias2, float* __restrict__ Out, int ostride) {
  extern __shared__ float smem[];
  const uint32_t sb = (uint32_t)__cvta_generic_to_shared(smem);

  const int tid = threadIdx.x;
  const int m0 = blockIdx.y * BM;
  const int col0 = blockIdx.x * BN;
  const int sec = col0 >> 9;
  const int n0 = col0 & 511;
  const float* W = (sec == 0) ? W0 : ((sec == 1) ? W1 : W2);
  const float* bias = (sec == 0) ? bias0 : ((sec == 1) ? bias1 : bias2);

  const int warp = tid >> 5, lane = tid & 31;
  const int g = lane >> 2, t = lane & 3;
  const int warp_m = (warp >> 2) * 64;  // 2 warps in m
  const int warp_n = (warp & 3) * 32;   // 4 warps in n

  // ldmatrix per-lane source row/byte (x4: lanes 0-7 m0, 8-15 m1, 16-23 m2, 24-31 m3)
  const int a_lm_row = warp_m + (lane & 7) + ((lane >> 3) & 1) * 8;
  const uint32_t a_lm_byte = ((lane >> 4) & 1) * 16;
  const uint32_t a_lane_off =
      (uint32_t)(a_lm_row * (SA_STRIDE * 4)) + a_lm_byte;

  float acc[4][4][4];
#pragma unroll
  for (int i = 0; i < 4; i++)
#pragma unroll
    for (int j = 0; j < 4; j++)
#pragma unroll
      for (int r = 0; r < 4; r++) acc[i][j][r] = 0.f;

  auto issue_stage = [&](int it) {
    float* as = smem + (it % STAGES) * STAGE_F;
    float* bs = as + A_STAGE;
    const int k0 = it * BK;
#pragma unroll
    for (int i = 0; i < 4; i++) {
      int cid = tid + i * 256;
      int row = cid >> 3, q = (cid & 7) * 4;
      cp_async16(as + row * SA_STRIDE + q,
                 A + (size_t)(m0 + row) * Dd + k0 + q);
    }
#pragma unroll
    for (int i = 0; i < 4; i++) {
      int cid = tid + i * 256;
      int row = cid >> 5, q = (cid & 31) * 4;
      cp_async16(bs + row * SB_STRIDE + q,
                 W + (size_t)(k0 + row) * Dd + n0 + q);
    }
    cp_commit();
  };

  issue_stage(0);
  issue_stage(1);

  for (int it = 0; it < KITERS; it++) {
    if (it < KITERS - 1)
      asm volatile("cp.async.wait_group 1;" ::: "memory");
    else
      asm volatile("cp.async.wait_group 0;" ::: "memory");
    __syncthreads();  // single barrier per iter
    if (it + 2 < KITERS) issue_stage(it + 2);

    const uint32_t a_base =
        sb + (uint32_t)((it % STAGES) * STAGE_F * 4) + a_lane_off;
    const float* bs = smem + (it % STAGES) * STAGE_F + A_STAGE;

    // fragment ping-pong: load frags(ks+1) before MMAs(ks)
    uint32_t af[2][4][4], bf[2][4][2];

    auto load_frags = [&](int buf, int ks) {
#pragma unroll
      for (int mi = 0; mi < 4; mi++) {
        ldmatrix_x4(af[buf][mi], a_base + mi * (16 * SA_STRIDE * 4) + ks * 4);
        if (CVT_A) {
#pragma unroll
          for (int r = 0; r < 4; r++) af[buf][mi][r] = cvt_u(af[buf][mi][r]);
        }
      }
#pragma unroll
      for (int ni = 0; ni < 4; ni++) {
        const float* bp = bs + (ks + t) * SB_STRIDE + warp_n + ni * 8 + g;
        bf[buf][ni][0] = __float_as_uint(bp[0]);
        bf[buf][ni][1] = __float_as_uint(bp[4 * SB_STRIDE]);
      }
    };

    load_frags(0, 0);
#pragma unroll
    for (int kg = 0; kg < 4; kg++) {
      const int cur = kg & 1, nxt = cur ^ 1;
      if (kg < 3) load_frags(nxt, (kg + 1) * 8);
#pragma unroll
      for (int mi = 0; mi < 4; mi++)
#pragma unroll
        for (int ni = 0; ni < 4; ni++)
          mma_tf32(acc[mi][ni], af[cur][mi][0], af[cur][mi][1],
                   af[cur][mi][2], af[cur][mi][3], bf[cur][ni][0],
                   bf[cur][ni][1]);
    }
  }

  // epilogue: bias + store
#pragma unroll
  for (int mi = 0; mi < 4; mi++) {
    int r0 = m0 + warp_m + mi * 16 + g;
#pragma unroll
    for (int ni = 0; ni < 4; ni++) {
      int c = col0 + warp_n + ni * 8 + 2 * t;
      float b0v = bias[c & 511], b1v = bias[(c & 511) + 1];
      float2 v0 = make_float2(acc[mi][ni][0] + b0v, acc[mi][ni][1] + b1v);
      float2 v1 = make_float2(acc[mi][ni][2] + b0v, acc[mi][ni][3] + b1v);
      *reinterpret_cast<float2*>(Out + (size_t)r0 * ostride + c) = v0;
      *reinterpret_cast<float2*>(Out + (size_t)(r0 + 8) * ostride + c) = v1;
    }
  }
}

// Fused weight pre-round: one launch, blockIdx.y picks the weight matrix.
__global__ void rna_w_kernel(const float* __restrict__ Wq,
                             const float* __restrict__ Wk,
                             const float* __restrict__ Wv,
                             const float* __restrict__ Wo) {
  const int w = blockIdx.y;
  const float* src = (w == 0) ? Wq : (w == 1) ? Wk : (w == 2) ? Wv : Wo;
  float* dst = g_Wr + (size_t)w * 262144;
  int i = blockIdx.x * blockDim.x + threadIdx.x;
  float4 v = reinterpret_cast<const float4*>(src)[i];
  v.x = to_tf32(v.x); v.y = to_tf32(v.y); v.z = to_tf32(v.z); v.w = to_tf32(v.w);
  reinterpret_cast<float4*>(dst)[i] = v;
}

// 512 threads, 2 batches per CTA; warp (h within half) = head h.
__global__ __launch_bounds__(512) void attn_kernel(const float* __restrict__ pb) {
  __shared__ float sX[2][Ss * 1536];
  __shared__ float sA[2][Hh][Ss][Ss];
  const int b2 = blockIdx.x;
  const int tid = threadIdx.x;
  const float* src = g_QKV + (size_t)b2 * (2 * Ss * 1536);

  for (int i = tid; i < 2 * Ss * 1536 / 4; i += 512)
    reinterpret_cast<float4*>(&sX[0][0])[i] =
        reinterpret_cast<const float4*>(src)[i];
  __syncthreads();

  const int half = tid >> 8;
  const int h = (tid >> 5) & 7, lane = tid & 31;
  const int c0 = h * HDd;
  const float* X = sX[half];
  float (*Arow)[Ss] = sA[half][h];

  if (lane < Ss * Ss) {
    int s = lane / Ss, tt = lane % Ss;
    float a = 0.f;
#pragma unroll
    for (int d = 0; d < HDd; d++)
      a += X[s * 1536 + c0 + d] * X[tt * 1536 + 512 + c0 + d];
    Arow[s][tt] = a * 0.125f + pb[(h * Ss + s) * Ss + tt];
  }
  __syncwarp();

  if (lane < Ss) {
    float m = Arow[lane][0];
#pragma unroll
    for (int tt = 1; tt < Ss; tt++) m = fmaxf(m, Arow[lane][tt]);
    float e[Ss], sum = 0.f;
#pragma unroll
    for (int tt = 0; tt < Ss; tt++) {
      e[tt] = expf(Arow[lane][tt] - m);
      sum += e[tt];
    }
    float inv = 1.0f / sum;
#pragma unroll
    for (int tt = 0; tt < Ss; tt++) Arow[lane][tt] = e[tt] * inv;
  }
  __syncwarp();

  float* dst = g_O + ((size_t)b2 * 2 + half) * (Ss * Dd);
#pragma unroll
  for (int s = 0; s < Ss; s++) {
    float o0 = 0.f, o1 = 0.f;
#pragma unroll
    for (int tt = 0; tt < Ss; tt++) {
      float a = Arow[s][tt];
      o0 += a * X[tt * 1536 + 1024 + c0 + lane];
      o1 += a * X[tt * 1536 + 1024 + c0 + lane + 32];
    }
    dst[s * Dd + c0 + lane] = to_tf32(o0);
    dst[s * Dd + c0 + lane + 32] = to_tf32(o1);
  }
}

extern "C" void kernel_launch(void* const* d_in, const int* in_sizes, int n_in,
                              void* d_out, int out_size) {
  (void)in_sizes; (void)n_in; (void)out_size;
  const float* x  = (const float*)d_in[0];
  const float* Wq = (const float*)d_in[1];
  const float* bq = (const float*)d_in[2];
  const float* Wk = (const float*)d_in[3];
  const float* bk = (const float*)d_in[4];
  const float* Wv = (const float*)d_in[5];
  const float* bv = (const float*)d_in[6];
  const float* Wo = (const float*)d_in[7];
  const float* bo = (const float*)d_in[8];
  const float* pb = (const float*)d_in[9];
  float* out = (float*)d_out;

  cudaFuncSetAttribute(gemm_tf32_kernel<true>,
                       cudaFuncAttributeMaxDynamicSharedMemorySize, SMEM_BYTES);
  cudaFuncSetAttribute(gemm_tf32_kernel<false>,
                       cudaFuncAttributeMaxDynamicSharedMemorySize, SMEM_BYTES);

  void *qkv = nullptr, *op = nullptr, *wr = nullptr;
  cudaGetSymbolAddress(&qkv, g_QKV);
  cudaGetSymbolAddress(&op, g_O);
  cudaGetSymbolAddress(&wr, g_Wr);
  float* Wr = (float*)wr;

  // 0) pre-round weights to tf32 (single launch)
  rna_w_kernel<<<dim3(256, 4), 256>>>(Wq, Wk, Wv, Wo);

  // 1) fused QKV projection: rna(x) @ [Wq|Wk|Wv] -> g_QKV [m][1536]
  gemm_tf32_kernel<true><<<dim3(1536 / BN, Mm / BM), 256, SMEM_BYTES>>>(
      x, Wr + 0 * 262144, Wr + 1 * 262144, Wr + 2 * 262144,
      bq, bk, bv, (float*)qkv, 1536);
  // 2) attention, 2 batches per CTA
  attn_kernel<<<Bb / 2, 512>>>(pb);
  // 3) output projection: g_O (already rna'd) @ Wo -> d_out
  gemm_tf32_kernel<false><<<dim3(512 / BN, Mm / BM), 256, SMEM_BYTES>>>(
      (const float*)op, Wr + 3 * 262144, Wr + 3 * 262144, Wr + 3 * 262144,
      bo, bo, bo, out, 512);
}

// round 13
// speedup vs baseline: 1.2055x; 1.1159x over previous
#include <cuda_runtime.h>
#include <cstdint>

namespace {
constexpr int Bb = 16384, Ss = 5, Dd = 512, Hh = 8, HDd = 64;
constexpr int Mm = Bb * Ss;               // 81920
constexpr int BM = 128, BN = 128, BK = 32;
constexpr int KITERS = Dd / BK;           // 16
constexpr int SA_STRIDE = 36;             // 144B rows: ldmatrix phases conflict-free
constexpr int SB_STRIDE = 136;            // conflict-free b-frag LDS (8t+g)
constexpr int A_STAGE = BM * SA_STRIDE;   // 4608 floats
constexpr int B_STAGE = BK * SB_STRIDE;   // 4352 floats
constexpr int STAGE_F = A_STAGE + B_STAGE;        // 8960 floats = 35840 B
constexpr int STAGES = 3;
constexpr int SMEM_BYTES = STAGES * STAGE_F * 4;  // 107520 B
}

// Scratch (device globals: allocation-free rule)
__device__ float g_QKV[(size_t)Mm * 1536];  // [m][ q | k | v ]
__device__ float g_O[(size_t)Mm * Dd];      // rna(attn out)

__device__ __forceinline__ float to_tf32(float x) {
  float y;
  asm("cvt.rna.tf32.f32 %0, %1;" : "=f"(y) : "f"(x));
  return y;
}
__device__ __forceinline__ uint32_t cvt_u(uint32_t x) {
  return __float_as_uint(to_tf32(__uint_as_float(x)));
}

__device__ __forceinline__ void mma_tf32(float c[4], uint32_t a0, uint32_t a1,
                                         uint32_t a2, uint32_t a3,
                                         uint32_t b0, uint32_t b1) {
  asm volatile(
      "mma.sync.aligned.m16n8k8.row.col.f32.tf32.tf32.f32 "
      "{%0,%1,%2,%3}, {%4,%5,%6,%7}, {%8,%9}, {%0,%1,%2,%3};"
      : "+f"(c[0]), "+f"(c[1]), "+f"(c[2]), "+f"(c[3])
      : "r"(a0), "r"(a1), "r"(a2), "r"(a3), "r"(b0), "r"(b1));
}

__device__ __forceinline__ void ldmatrix_x4(uint32_t r[4], uint32_t addr) {
  asm volatile(
      "ldmatrix.sync.aligned.m8n8.x4.shared.b16 {%0,%1,%2,%3}, [%4];"
      : "=r"(r[0]), "=r"(r[1]), "=r"(r[2]), "=r"(r[3])
      : "r"(addr));
}

__device__ __forceinline__ void cp_async16(void* smem_ptr, const void* gptr) {
  uint32_t saddr = (uint32_t)__cvta_generic_to_shared(smem_ptr);
  asm volatile("cp.async.cg.shared.global [%0], [%1], 16;" ::"r"(saddr),
               "l"(gptr));
}
__device__ __forceinline__ void cp_commit() {
  asm volatile("cp.async.commit_group;" ::);
}

// Out[:, col0:col0+128] = A[M,512] @ W_sec[512,512] + bias_sec
// CVT_A / CVT_B: round fragments to tf32 (rna) in-loop.
template <bool CVT_A, bool CVT_B>
__global__ __launch_bounds__(256, 2) void gemm_tf32_kernel(
    const float* __restrict__ A, const float* __restrict__ W0,
    const float* __restrict__ W1, const float* __restrict__ W2,
    const float* __restrict__ bias0, const float* __restrict__ bias1,
    const float* __restrict__ bias2, float* __restrict__ Out, int ostride) {
  extern __shared__ float smem[];
  const uint32_t sb = (uint32_t)__cvta_generic_to_shared(smem);

  const int tid = threadIdx.x;
  const int m0 = blockIdx.y * BM;
  const int col0 = blockIdx.x * BN;
  const int sec = col0 >> 9;
  const int n0 = col0 & 511;
  const float* W = (sec == 0) ? W0 : ((sec == 1) ? W1 : W2);
  const float* bias = (sec == 0) ? bias0 : ((sec == 1) ? bias1 : bias2);

  const int warp = tid >> 5, lane = tid & 31;
  const int g = lane >> 2, t = lane & 3;
  const int warp_m = (warp >> 2) * 64;  // 2 warps in m
  const int warp_n = (warp & 3) * 32;   // 4 warps in n

  // ldmatrix per-lane source row/byte (x4: lanes 0-7 m0, 8-15 m1, 16-23 m2, 24-31 m3)
  const int a_lm_row = warp_m + (lane & 7) + ((lane >> 3) & 1) * 8;
  const uint32_t a_lm_byte = ((lane >> 4) & 1) * 16;
  const uint32_t a_lane_off =
      (uint32_t)(a_lm_row * (SA_STRIDE * 4)) + a_lm_byte;

  float acc[4][4][4];
#pragma unroll
  for (int i = 0; i < 4; i++)
#pragma unroll
    for (int j = 0; j < 4; j++)
#pragma unroll
      for (int r = 0; r < 4; r++) acc[i][j][r] = 0.f;

  auto issue_stage = [&](int it) {
    float* as = smem + (it % STAGES) * STAGE_F;
    float* bs = as + A_STAGE;
    const int k0 = it * BK;
#pragma unroll
    for (int i = 0; i < 4; i++) {
      int cid = tid + i * 256;
      int row = cid >> 3, q = (cid & 7) * 4;
      cp_async16(as + row * SA_STRIDE + q,
                 A + (size_t)(m0 + row) * Dd + k0 + q);
    }
#pragma unroll
    for (int i = 0; i < 4; i++) {
      int cid = tid + i * 256;
      int row = cid >> 5, q = (cid & 31) * 4;
      cp_async16(bs + row * SB_STRIDE + q,
                 W + (size_t)(k0 + row) * Dd + n0 + q);
    }
    cp_commit();
  };

  issue_stage(0);
  issue_stage(1);

  for (int it = 0; it < KITERS; it++) {
    if (it < KITERS - 1)
      asm volatile("cp.async.wait_group 1;" ::: "memory");
    else
      asm volatile("cp.async.wait_group 0;" ::: "memory");
    __syncthreads();  // single barrier per iter
    if (it + 2 < KITERS) issue_stage(it + 2);

    const uint32_t a_base =
        sb + (uint32_t)((it % STAGES) * STAGE_F * 4) + a_lane_off;
    const float* bs = smem + (it % STAGES) * STAGE_F + A_STAGE;
#pragma unroll
    for (int ks = 0; ks < BK; ks += 8) {
      uint32_t af[4][4], bf[4][2];
#pragma unroll
      for (int mi = 0; mi < 4; mi++) {
        ldmatrix_x4(af[mi], a_base + mi * (16 * SA_STRIDE * 4) + ks * 4);
        if (CVT_A) {
#pragma unroll
          for (int r = 0; r < 4; r++) af[mi][r] = cvt_u(af[mi][r]);
        }
      }
#pragma unroll
      for (int ni = 0; ni < 4; ni++) {
        const float* bp = bs + (ks + t) * SB_STRIDE + warp_n + ni * 8 + g;
        bf[ni][0] = __float_as_uint(bp[0]);
        bf[ni][1] = __float_as_uint(bp[4 * SB_STRIDE]);
        if (CVT_B) {
          bf[ni][0] = cvt_u(bf[ni][0]);
          bf[ni][1] = cvt_u(bf[ni][1]);
        }
      }
#pragma unroll
      for (int mi = 0; mi < 4; mi++)
#pragma unroll
        for (int ni = 0; ni < 4; ni++)
          mma_tf32(acc[mi][ni], af[mi][0], af[mi][1], af[mi][2], af[mi][3],
                   bf[ni][0], bf[ni][1]);
    }
  }

  // epilogue: bias + store
#pragma unroll
  for (int mi = 0; mi < 4; mi++) {
    int r0 = m0 + warp_m + mi * 16 + g;
#pragma unroll
    for (int ni = 0; ni < 4; ni++) {
      int c = col0 + warp_n + ni * 8 + 2 * t;
      float b0v = bias[c & 511], b1v = bias[(c & 511) + 1];
      float2 v0 = make_float2(acc[mi][ni][0] + b0v, acc[mi][ni][1] + b1v);
      float2 v1 = make_float2(acc[mi][ni][2] + b0v, acc[mi][ni][3] + b1v);
      *reinterpret_cast<float2*>(Out + (size_t)r0 * ostride + c) = v0;
      *reinterpret_cast<float2*>(Out + (size_t)(r0 + 8) * ostride + c) = v1;
    }
  }
}

// Warp-per-(batch,head) attention: no smem, no barriers, register-resident.
// CTA = 8 warps = all 8 heads of batch blockIdx.x.
__global__ __launch_bounds__(256) void attn_kernel(const float* __restrict__ pb) {
  const int b = blockIdx.x;
  const int h = threadIdx.x >> 5, lane = threadIdx.x & 31;
  const int c0 = h * HDd;
  const float* base = g_QKV + (size_t)b * (Ss * 1536);

  // Register-load q,k,v head slices: 30 independent coalesced LDGs.
  float q[Ss][2], k[Ss][2], v[Ss][2];
#pragma unroll
  for (int r = 0; r < Ss; r++) {
    const float* row = base + r * 1536 + c0 + lane;
    q[r][0] = row[0];         q[r][1] = row[32];
    k[r][0] = row[512];       k[r][1] = row[512 + 32];
    v[r][0] = row[1024];      v[r][1] = row[1024 + 32];
  }

  // Own bias for lane<25 (lane = s*5+t)
  float pbv = 0.f;
  if (lane < Ss * Ss) pbv = pb[h * 25 + lane];

  // Partial dot products p[s*5+t], butterfly-reduce each; owner lane keeps.
  float p[25];
#pragma unroll
  for (int s = 0; s < Ss; s++)
#pragma unroll
    for (int tt = 0; tt < Ss; tt++)
      p[s * 5 + tt] = q[s][0] * k[tt][0] + q[s][1] * k[tt][1];

  float sc = 0.f;
#pragma unroll
  for (int i = 0; i < 25; i++) {
    float r = p[i];
    r += __shfl_xor_sync(0xffffffffu, r, 16);
    r += __shfl_xor_sync(0xffffffffu, r, 8);
    r += __shfl_xor_sync(0xffffffffu, r, 4);
    r += __shfl_xor_sync(0xffffffffu, r, 2);
    r += __shfl_xor_sync(0xffffffffu, r, 1);
    if (lane == i) sc = r;
  }
  sc = sc * 0.125f + pbv;  // scale 1/sqrt(64) + prop bias

  // Softmax on owner lanes (rows of 5 lanes)
  const int s_own = lane / 5;  // row for lanes 0..24 (garbage above, unused)
  float mx = -1e30f;
#pragma unroll
  for (int j = 0; j < Ss; j++)
    mx = fmaxf(mx, __shfl_sync(0xffffffffu, sc, s_own * 5 + j));
  float e = __expf(sc - mx);
  float sum = 0.f;
#pragma unroll
  for (int j = 0; j < Ss; j++)
    sum += __shfl_sync(0xffffffffu, e, s_own * 5 + j);
  float a_own = e / sum;

  // Output: o[s][c] = sum_t a[s][t] * v[t][c]; broadcast a via shfl.
  float* dst = g_O + (size_t)b * (Ss * Dd) + c0 + lane;
#pragma unroll
  for (int s = 0; s < Ss; s++) {
    float o0 = 0.f, o1 = 0.f;
#pragma unroll
    for (int tt = 0; tt < Ss; tt++) {
      float a = __shfl_sync(0xffffffffu, a_own, s * 5 + tt);
      o0 += a * v[tt][0];
      o1 += a * v[tt][1];
    }
    dst[s * Dd] = to_tf32(o0);
    dst[s * Dd + 32] = to_tf32(o1);
  }
}

extern "C" void kernel_launch(void* const* d_in, const int* in_sizes, int n_in,
                              void* d_out, int out_size) {
  (void)in_sizes; (void)n_in; (void)out_size;
  const float* x  = (const float*)d_in[0];
  const float* Wq = (const float*)d_in[1];
  const float* bq = (const float*)d_in[2];
  const float* Wk = (const float*)d_in[3];
  const float* bk = (const float*)d_in[4];
  const float* Wv = (const float*)d_in[5];
  const float* bv = (const float*)d_in[6];
  const float* Wo = (const float*)d_in[7];
  const float* bo = (const float*)d_in[8];
  const float* pb = (const float*)d_in[9];
  float* out = (float*)d_out;

  cudaFuncSetAttribute(gemm_tf32_kernel<true, true>,
                       cudaFuncAttributeMaxDynamicSharedMemorySize, SMEM_BYTES);
  cudaFuncSetAttribute(gemm_tf32_kernel<false, true>,
                       cudaFuncAttributeMaxDynamicSharedMemorySize, SMEM_BYTES);

  void *qkv = nullptr, *op = nullptr;
  cudaGetSymbolAddress(&qkv, g_QKV);
  cudaGetSymbolAddress(&op, g_O);

  // 1) fused QKV projection: rna(x) @ rna([Wq|Wk|Wv]) -> g_QKV [m][1536]
  gemm_tf32_kernel<true, true><<<dim3(1536 / BN, Mm / BM), 256, SMEM_BYTES>>>(
      x, Wq, Wk, Wv, bq, bk, bv, (float*)qkv, 1536);
  // 2) attention: warp per (batch, head)
  attn_kernel<<<Bb, 256>>>(pb);
  // 3) output projection: g_O (pre-rounded) @ rna(Wo) -> d_out
  gemm_tf32_kernel<false, true><<<dim3(512 / BN, Mm / BM), 256, SMEM_BYTES>>>(
      (const float*)op, Wo, Wo, Wo, bo, bo, bo, out, 512);
}

// round 14
// speedup vs baseline: 1.2565x; 1.0422x over previous
#include <cuda_runtime.h>
#include <cstdint>

namespace {
constexpr int Bb = 16384, Ss = 5, Dd = 512, Hh = 8, HDd = 64;
constexpr int Mm = Bb * Ss;               // 81920
constexpr int BM = 128, BN = 128, BK = 32;
constexpr int KITERS = Dd / BK;           // 16
constexpr int SA_STRIDE = 36;             // 144B rows: ldmatrix phases conflict-free
constexpr int SB_STRIDE = 136;            // conflict-free b-frag LDS (8t+g)
constexpr int A_STAGE = BM * SA_STRIDE;   // 4608 floats
constexpr int B_STAGE = BK * SB_STRIDE;   // 4352 floats
constexpr int STAGE_F = A_STAGE + B_STAGE;        // 8960 floats = 35840 B
constexpr int STAGES = 3;
constexpr int SMEM_BYTES = STAGES * STAGE_F * 4;  // 107520 B
}

// Scratch (device globals: allocation-free rule)
__device__ float g_QKV[(size_t)Mm * 1536];  // [m][ q | k | v ]
__device__ float g_O[(size_t)Mm * Dd];      // rna(attn out)
__device__ float g_Wr[4 * 512 * 512];       // rna(Wq|Wk|Wv|Wo), [k][n] layout

__device__ __forceinline__ float to_tf32(float x) {
  float y;
  asm("cvt.rna.tf32.f32 %0, %1;" : "=f"(y) : "f"(x));
  return y;
}
__device__ __forceinline__ uint32_t cvt_u(uint32_t x) {
  return __float_as_uint(to_tf32(__uint_as_float(x)));
}

__device__ __forceinline__ void mma_tf32(float c[4], uint32_t a0, uint32_t a1,
                                         uint32_t a2, uint32_t a3,
                                         uint32_t b0, uint32_t b1) {
  asm volatile(
      "mma.sync.aligned.m16n8k8.row.col.f32.tf32.tf32.f32 "
      "{%0,%1,%2,%3}, {%4,%5,%6,%7}, {%8,%9}, {%0,%1,%2,%3};"
      : "+f"(c[0]), "+f"(c[1]), "+f"(c[2]), "+f"(c[3])
      : "r"(a0), "r"(a1), "r"(a2), "r"(a3), "r"(b0), "r"(b1));
}

__device__ __forceinline__ void ldmatrix_x4(uint32_t r[4], uint32_t addr) {
  asm volatile(
      "ldmatrix.sync.aligned.m8n8.x4.shared.b16 {%0,%1,%2,%3}, [%4];"
      : "=r"(r[0]), "=r"(r[1]), "=r"(r[2]), "=r"(r[3])
      : "r"(addr));
}

__device__ __forceinline__ void cp_async16(void* smem_ptr, const void* gptr) {
  uint32_t saddr = (uint32_t)__cvta_generic_to_shared(smem_ptr);
  asm volatile("cp.async.cg.shared.global [%0], [%1], 16;" ::"r"(saddr),
               "l"(gptr));
}
__device__ __forceinline__ void cp_commit() {
  asm volatile("cp.async.commit_group;" ::);
}

// Out[:, col0:col0+128] = A[M,512] @ W_sec[512,512] + bias_sec
// W is PRE-ROUNDED tf32 ([k][n]). CVT_A: rna A fragments in-loop.
template <bool CVT_A>
__global__ __launch_bounds__(256, 2) void gemm_tf32_kernel(
    const float* __restrict__ A, const float* __restrict__ W0,
    const float* __restrict__ W1, const float* __restrict__ W2,
    const float* __restrict__ bias0, const float* __restrict__ bias1,
    const float* __restrict__ bias2, float* __restrict__ Out, int ostride) {
  extern __shared__ float smem[];
  const uint32_t sb = (uint32_t)__cvta_generic_to_shared(smem);

  const int tid = threadIdx.x;
  const int m0 = blockIdx.y * BM;
  const int col0 = blockIdx.x * BN;
  const int sec = col0 >> 9;
  const int n0 = col0 & 511;
  const float* W = (sec == 0) ? W0 : ((sec == 1) ? W1 : W2);
  const float* bias = (sec == 0) ? bias0 : ((sec == 1) ? bias1 : bias2);

  const int warp = tid >> 5, lane = tid & 31;
  const int g = lane >> 2, t = lane & 3;
  const int warp_m = (warp >> 2) * 64;  // 2 warps in m
  const int warp_n = (warp & 3) * 32;   // 4 warps in n

  // ldmatrix per-lane source row/byte (x4: lanes 0-7 m0, 8-15 m1, 16-23 m2, 24-31 m3)
  const int a_lm_row = warp_m + (lane & 7) + ((lane >> 3) & 1) * 8;
  const uint32_t a_lm_byte = ((lane >> 4) & 1) * 16;
  const uint32_t a_lane_off =
      (uint32_t)(a_lm_row * (SA_STRIDE * 4)) + a_lm_byte;

  float acc[4][4][4];
#pragma unroll
  for (int i = 0; i < 4; i++)
#pragma unroll
    for (int j = 0; j < 4; j++)
#pragma unroll
      for (int r = 0; r < 4; r++) acc[i][j][r] = 0.f;

  auto issue_stage = [&](int it) {
    float* as = smem + (it % STAGES) * STAGE_F;
    float* bs = as + A_STAGE;
    const int k0 = it * BK;
#pragma unroll
    for (int i = 0; i < 4; i++) {
      int cid = tid + i * 256;
      int row = cid >> 3, q = (cid & 7) * 4;
      cp_async16(as + row * SA_STRIDE + q,
                 A + (size_t)(m0 + row) * Dd + k0 + q);
    }
#pragma unroll
    for (int i = 0; i < 4; i++) {
      int cid = tid + i * 256;
      int row = cid >> 5, q = (cid & 31) * 4;
      cp_async16(bs + row * SB_STRIDE + q,
                 W + (size_t)(k0 + row) * Dd + n0 + q);
    }
    cp_commit();
  };

  issue_stage(0);
  issue_stage(1);

  for (int it = 0; it < KITERS; it++) {
    if (it < KITERS - 1)
      asm volatile("cp.async.wait_group 1;" ::: "memory");
    else
      asm volatile("cp.async.wait_group 0;" ::: "memory");
    __syncthreads();  // single barrier per iter
    if (it + 2 < KITERS) issue_stage(it + 2);

    const uint32_t a_base =
        sb + (uint32_t)((it % STAGES) * STAGE_F * 4) + a_lane_off;
    const float* bs = smem + (it % STAGES) * STAGE_F + A_STAGE;
#pragma unroll
    for (int ks = 0; ks < BK; ks += 8) {
      uint32_t af[4][4], bf[4][2];
#pragma unroll
      for (int mi = 0; mi < 4; mi++) {
        ldmatrix_x4(af[mi], a_base + mi * (16 * SA_STRIDE * 4) + ks * 4);
        if (CVT_A) {
#pragma unroll
          for (int r = 0; r < 4; r++) af[mi][r] = cvt_u(af[mi][r]);
        }
      }
#pragma unroll
      for (int ni = 0; ni < 4; ni++) {
        const float* bp = bs + (ks + t) * SB_STRIDE + warp_n + ni * 8 + g;
        bf[ni][0] = __float_as_uint(bp[0]);
        bf[ni][1] = __float_as_uint(bp[4 * SB_STRIDE]);
      }
#pragma unroll
      for (int mi = 0; mi < 4; mi++)
#pragma unroll
        for (int ni = 0; ni < 4; ni++)
          mma_tf32(acc[mi][ni], af[mi][0], af[mi][1], af[mi][2], af[mi][3],
                   bf[ni][0], bf[ni][1]);
    }
  }

  // epilogue: bias + store
#pragma unroll
  for (int mi = 0; mi < 4; mi++) {
    int r0 = m0 + warp_m + mi * 16 + g;
#pragma unroll
    for (int ni = 0; ni < 4; ni++) {
      int c = col0 + warp_n + ni * 8 + 2 * t;
      float b0v = bias[c & 511], b1v = bias[(c & 511) + 1];
      float2 v0 = make_float2(acc[mi][ni][0] + b0v, acc[mi][ni][1] + b1v);
      float2 v1 = make_float2(acc[mi][ni][2] + b0v, acc[mi][ni][3] + b1v);
      *reinterpret_cast<float2*>(Out + (size_t)r0 * ostride + c) = v0;
      *reinterpret_cast<float2*>(Out + (size_t)(r0 + 8) * ostride + c) = v1;
    }
  }
}

// Fused weight pre-round: one launch, blockIdx.y picks the weight matrix.
__global__ void rna_w_kernel(const float* __restrict__ Wq,
                             const float* __restrict__ Wk,
                             const float* __restrict__ Wv,
                             const float* __restrict__ Wo) {
  const int w = blockIdx.y;
  const float* src = (w == 0) ? Wq : (w == 1) ? Wk : (w == 2) ? Wv : Wo;
  float* dst = g_Wr + (size_t)w * 262144;
  int i = blockIdx.x * blockDim.x + threadIdx.x;
  float4 v = reinterpret_cast<const float4*>(src)[i];
  v.x = to_tf32(v.x); v.y = to_tf32(v.y); v.z = to_tf32(v.z); v.w = to_tf32(v.w);
  reinterpret_cast<float4*>(dst)[i] = v;
}

// Warp-per-(batch,head) attention: no smem, no barriers, register-resident.
__global__ __launch_bounds__(256) void attn_kernel(const float* __restrict__ pb) {
  const int b = blockIdx.x;
  const int h = threadIdx.x >> 5, lane = threadIdx.x & 31;
  const int c0 = h * HDd;
  const float* base = g_QKV + (size_t)b * (Ss * 1536);

  float q[Ss][2], k[Ss][2], v[Ss][2];
#pragma unroll
  for (int r = 0; r < Ss; r++) {
    const float* row = base + r * 1536 + c0 + lane;
    q[r][0] = row[0];         q[r][1] = row[32];
    k[r][0] = row[512];       k[r][1] = row[512 + 32];
    v[r][0] = row[1024];      v[r][1] = row[1024 + 32];
  }

  float pbv = 0.f;
  if (lane < Ss * Ss) pbv = pb[h * 25 + lane];

  float p[25];
#pragma unroll
  for (int s = 0; s < Ss; s++)
#pragma unroll
    for (int tt = 0; tt < Ss; tt++)
      p[s * 5 + tt] = q[s][0] * k[tt][0] + q[s][1] * k[tt][1];

  float sc = 0.f;
#pragma unroll
  for (int i = 0; i < 25; i++) {
    float r = p[i];
    r += __shfl_xor_sync(0xffffffffu, r, 16);
    r += __shfl_xor_sync(0xffffffffu, r, 8);
    r += __shfl_xor_sync(0xffffffffu, r, 4);
    r += __shfl_xor_sync(0xffffffffu, r, 2);
    r += __shfl_xor_sync(0xffffffffu, r, 1);
    if (lane == i) sc = r;
  }
  sc = sc * 0.125f + pbv;

  const int s_own = lane / 5;
  float mx = -1e30f;
#pragma unroll
  for (int j = 0; j < Ss; j++)
    mx = fmaxf(mx, __shfl_sync(0xffffffffu, sc, s_own * 5 + j));
  float e = __expf(sc - mx);
  float sum = 0.f;
#pragma unroll
  for (int j = 0; j < Ss; j++)
    sum += __shfl_sync(0xffffffffu, e, s_own * 5 + j);
  float a_own = e / sum;

  float* dst = g_O + (size_t)b * (Ss * Dd) + c0 + lane;
#pragma unroll
  for (int s = 0; s < Ss; s++) {
    float o0 = 0.f, o1 = 0.f;
#pragma unroll
    for (int tt = 0; tt < Ss; tt++) {
      float a = __shfl_sync(0xffffffffu, a_own, s * 5 + tt);
      o0 += a * v[tt][0];
      o1 += a * v[tt][1];
    }
    dst[s * Dd] = to_tf32(o0);
    dst[s * Dd + 32] = to_tf32(o1);
  }
}

extern "C" void kernel_launch(void* const* d_in, const int* in_sizes, int n_in,
                              void* d_out, int out_size) {
  (void)in_sizes; (void)n_in; (void)out_size;
  const float* x  = (const float*)d_in[0];
  const float* Wq = (const float*)d_in[1];
  const float* bq = (const float*)d_in[2];
  const float* Wk = (const float*)d_in[3];
  const float* bk = (const float*)d_in[4];
  const float* Wv = (const float*)d_in[5];
  const float* bv = (const float*)d_in[6];
  const float* Wo = (const float*)d_in[7];
  const float* bo = (const float*)d_in[8];
  const float* pb = (const float*)d_in[9];
  float* out = (float*)d_out;

  cudaFuncSetAttribute(gemm_tf32_kernel<true>,
                       cudaFuncAttributeMaxDynamicSharedMemorySize, SMEM_BYTES);
  cudaFuncSetAttribute(gemm_tf32_kernel<false>,
                       cudaFuncAttributeMaxDynamicSharedMemorySize, SMEM_BYTES);

  void *qkv = nullptr, *op = nullptr, *wr = nullptr;
  cudaGetSymbolAddress(&qkv, g_QKV);
  cudaGetSymbolAddress(&op, g_O);
  cudaGetSymbolAddress(&wr, g_Wr);
  float* Wr = (float*)wr;

  // 0) pre-round weights to tf32 (one launch, ~15us)
  rna_w_kernel<<<dim3(256, 4), 256>>>(Wq, Wk, Wv, Wo);

  // 1) fused QKV projection: rna(x) in-loop @ prep'd W -> g_QKV [m][1536]
  gemm_tf32_kernel<true><<<dim3(1536 / BN, Mm / BM), 256, SMEM_BYTES>>>(
      x, Wr + 0 * 262144, Wr + 1 * 262144, Wr + 2 * 262144,
      bq, bk, bv, (float*)qkv, 1536);
  // 2) attention: warp per (batch, head)
  attn_kernel<<<Bb, 256>>>(pb);
  // 3) output projection: g_O (pre-rounded) @ prep'd Wo -> d_out, CVT-free
  gemm_tf32_kernel<false><<<dim3(512 / BN, Mm / BM), 256, SMEM_BYTES>>>(
      (const float*)op, Wr + 3 * 262144, Wr + 3 * 262144, Wr + 3 * 262144,
      bo, bo, bo, out, 512);
}